// round 8
// baseline (speedup 1.0000x reference)
#include <cuda_runtime.h>
#include <cuda_fp16.h>
#include <cstdint>

// Problem constants (fixed instance)
#define NN    100000
#define NPAD  100096          // 782 * 128
#define C     256
#define NSETS 4
#define EMAX  500000
#define NT    (NSETS * NN)    // 400000 (deg/offset table size)
#define NBLK  ((NT + 1023) / 1024)   // 391 scan blocks

// Persistent scratch (device globals — no allocation allowed)
__device__ __half   g_h[(size_t)NSETS * NPAD * C];   // ~205 MB fp16 H_s
__device__ uint32_t g_xtf[(size_t)NPAD * C];         // ~102 MB x pre-converted to tf32 bits
__device__ float    g_dis[NT];                       // rsqrt(deg)
__device__ int      g_deg[NT];                       // 1 + in-edge count
__device__ int      g_off[NT];                       // CSR offsets (global over all sets)
__device__ int      g_cursor[NT];                    // fill cursors
__device__ int      g_rows[NSETS * EMAX];            // CSR: source rows bucketed by (s, col)
__device__ float    g_wsrc[NSETS * EMAX];            // CSR: dis[row] per edge (precomputed)
__device__ int      g_bsums[512];                    // scan block sums
__device__ uint32_t g_wcat[C * (NSETS * C)];         // [256][1024] fused weights, tf32 bits
__device__ float    g_bsum[C];                       // Σ_s b_s ⊙ p_{s+2}

__device__ __forceinline__ uint32_t f2tf32(float f) {
    uint32_t r;
    asm("cvt.rna.tf32.f32 %0, %1;" : "=r"(r) : "f"(f));
    return r;
}

// ---------------------------------------------------------------------------
// Prep: Wcat[k][s*256+n] = tf32(W_s[k][n]*p_{s+2}[n]); bias term; deg init = 1
// ---------------------------------------------------------------------------
__global__ void prep_kernel(const float* __restrict__ W1, const float* __restrict__ W2,
                            const float* __restrict__ W3, const float* __restrict__ W4,
                            const float* __restrict__ b1, const float* __restrict__ b2,
                            const float* __restrict__ b3, const float* __restrict__ b4,
                            const float* __restrict__ p2, const float* __restrict__ p3,
                            const float* __restrict__ p4, const float* __restrict__ p5) {
    int k = blockIdx.x;
    int n = threadIdx.x;
    g_wcat[k * 1024 + 0 * 256 + n] = f2tf32(W1[k * 256 + n] * p2[n]);
    g_wcat[k * 1024 + 1 * 256 + n] = f2tf32(W2[k * 256 + n] * p3[n]);
    g_wcat[k * 1024 + 2 * 256 + n] = f2tf32(W3[k * 256 + n] * p4[n]);
    g_wcat[k * 1024 + 3 * 256 + n] = f2tf32(W4[k * 256 + n] * p5[n]);
    if (k == 0)
        g_bsum[n] = b1[n] * p2[n] + b2[n] * p3[n] + b3[n] * p4[n] + b4[n] * p5[n];
    int idx = k * 256 + n;
    for (int i = idx; i < NT; i += 256 * 256) g_deg[i] = 1;
}

// ---------------------------------------------------------------------------
// x -> tf32 bits (vectorized)
// ---------------------------------------------------------------------------
__global__ void xcvt_kernel(const float* __restrict__ x, int n4) {
    int i = blockIdx.x * blockDim.x + threadIdx.x;
    if (i >= n4) return;
    float4 v = __ldg((const float4*)x + i);
    uint4 o = make_uint4(f2tf32(v.x), f2tf32(v.y), f2tf32(v.z), f2tf32(v.w));
    ((uint4*)g_xtf)[i] = o;
}

// ---------------------------------------------------------------------------
// Degree count
// ---------------------------------------------------------------------------
__global__ void deg_kernel(const int* __restrict__ e0, const int* __restrict__ e1,
                           const int* __restrict__ e2, const int* __restrict__ e3, int E) {
    int s = blockIdx.y;
    int e = blockIdx.x * blockDim.x + threadIdx.x;
    if (e >= E) return;
    const int* eg = (s == 0) ? e0 : (s == 1) ? e1 : (s == 2) ? e2 : e3;
    atomicAdd(&g_deg[s * NN + __ldg(&eg[E + e])], 1);
}

__global__ void dis_kernel() {
    int i = blockIdx.x * blockDim.x + threadIdx.x;
    if (i < NT) g_dis[i] = rsqrtf((float)g_deg[i]);
}

// ---------------------------------------------------------------------------
// Exclusive scan over edge counts (g_deg[i]-1), 3 passes
// ---------------------------------------------------------------------------
__global__ void scanA_kernel() {
    int t = threadIdx.x;
    int base = blockIdx.x * 1024 + t * 4;
    int s = 0;
#pragma unroll
    for (int k = 0; k < 4; k++) {
        int i = base + k;
        if (i < NT) s += g_deg[i] - 1;
    }
    __shared__ int sm[256];
    sm[t] = s;
    __syncthreads();
    for (int d = 128; d > 0; d >>= 1) {
        if (t < d) sm[t] += sm[t + d];
        __syncthreads();
    }
    if (t == 0) g_bsums[blockIdx.x] = sm[0];
}

__global__ void scanB_kernel() {
    int t = threadIdx.x;   // 512 threads
    __shared__ int sm[512];
    int v = (t < NBLK) ? g_bsums[t] : 0;
    sm[t] = v;
    __syncthreads();
    for (int d = 1; d < 512; d <<= 1) {
        int tmp = (t >= d) ? sm[t - d] : 0;
        __syncthreads();
        sm[t] += tmp;
        __syncthreads();
    }
    if (t < NBLK) g_bsums[t] = sm[t] - v;   // exclusive
}

__global__ void scanC_kernel() {
    int t = threadIdx.x;
    int base = blockIdx.x * 1024 + t * 4;
    int a[4], tsum = 0;
#pragma unroll
    for (int k = 0; k < 4; k++) {
        int i = base + k;
        a[k] = (i < NT) ? (g_deg[i] - 1) : 0;
        tsum += a[k];
    }
    __shared__ int sm[256];
    sm[t] = tsum;
    __syncthreads();
    for (int d = 1; d < 256; d <<= 1) {
        int tmp = (t >= d) ? sm[t - d] : 0;
        __syncthreads();
        sm[t] += tmp;
        __syncthreads();
    }
    int run = g_bsums[blockIdx.x] + sm[t] - tsum;
#pragma unroll
    for (int k = 0; k < 4; k++) {
        int i = base + k;
        if (i < NT) {
            g_off[i] = run;
            g_cursor[i] = run;
            run += a[k];
        }
    }
}

// ---------------------------------------------------------------------------
// Bucket edges: g_rows[pos] = source row, g_wsrc[pos] = dis[source]
// (dis is complete by the time this runs)
// ---------------------------------------------------------------------------
__global__ void fill_kernel(const int* __restrict__ e0, const int* __restrict__ e1,
                            const int* __restrict__ e2, const int* __restrict__ e3, int E) {
    int s = blockIdx.y;
    int e = blockIdx.x * blockDim.x + threadIdx.x;
    if (e >= E) return;
    const int* eg = (s == 0) ? e0 : (s == 1) ? e1 : (s == 2) ? e2 : e3;
    int row = __ldg(&eg[e]);
    int col = __ldg(&eg[E + e]);
    int pos = atomicAdd(&g_cursor[s * NN + col], 1);
    g_rows[pos] = row;
    g_wsrc[pos] = g_dis[s * NN + row];
}

// ---------------------------------------------------------------------------
// tf32 GEMM: H[s][v][n] = sum_k x[v][k] * Wcat[k][s*256+n], fp16 output
// ---------------------------------------------------------------------------
#define BM 128
#define BN 128
#define BK 32
#define LDA 36
#define LDB 136

static constexpr int SMEM_BYTES = (2 * BM * LDA + 2 * BK * LDB) * 4;  // 71680

__device__ __forceinline__ void cp_async16(uint32_t* smem_ptr, const uint32_t* gmem_ptr, int src_bytes) {
    uint32_t saddr = (uint32_t)__cvta_generic_to_shared(smem_ptr);
    asm volatile("cp.async.cg.shared.global [%0], [%1], 16, %2;\n"
                 :: "r"(saddr), "l"(gmem_ptr), "r"(src_bytes));
}

__global__ __launch_bounds__(256, 2) void gemm_kernel(int n_rows) {
    extern __shared__ uint32_t sm[];
    uint32_t* Asm[2] = { sm, sm + BM * LDA };
    uint32_t* Bsm[2] = { sm + 2 * BM * LDA, sm + 2 * BM * LDA + BK * LDB };

    const int tid   = threadIdx.x;
    const int lane  = tid & 31;
    const int warp  = tid >> 5;
    const int warpM = warp >> 2;   // 0..1
    const int warpN = warp & 3;    // 0..3
    const int m0 = blockIdx.y * BM;
    const int n0 = blockIdx.x * BN;

    float acc[4][4][4];
#pragma unroll
    for (int i = 0; i < 4; i++)
#pragma unroll
        for (int j = 0; j < 4; j++)
#pragma unroll
            for (int k = 0; k < 4; k++) acc[i][j][k] = 0.f;

    auto loadA = [&](int buf, int kb) {
#pragma unroll
        for (int p = 0; p < 4; p++) {
            int idx = tid + p * 256;
            int row = idx >> 3;
            int c4  = idx & 7;
            int gr  = m0 + row;
            const uint32_t* src = g_xtf + (size_t)gr * C + kb + c4 * 4;
            cp_async16(&Asm[buf][row * LDA + c4 * 4], src, gr < n_rows ? 16 : 0);
        }
    };
    auto loadB = [&](int buf, int kb) {
#pragma unroll
        for (int p = 0; p < 4; p++) {
            int idx = tid + p * 256;
            int row = idx >> 5;
            int c4  = idx & 31;
            const uint32_t* src = g_wcat + (size_t)(kb + row) * 1024 + n0 + c4 * 4;
            cp_async16(&Bsm[buf][row * LDB + c4 * 4], src, 16);
        }
    };

    loadA(0, 0); loadB(0, 0);
    asm volatile("cp.async.commit_group;\n");

#pragma unroll 1
    for (int kc = 0; kc < 8; kc++) {          // K = 256 = 8 * BK
        int cur = kc & 1;
        if (kc < 7) {
            loadA(cur ^ 1, (kc + 1) * BK);
            loadB(cur ^ 1, (kc + 1) * BK);
            asm volatile("cp.async.commit_group;\n");
            asm volatile("cp.async.wait_group 1;\n");
        } else {
            asm volatile("cp.async.wait_group 0;\n");
        }
        __syncthreads();

        const uint32_t* Ab = Asm[cur];
        const uint32_t* Bb = Bsm[cur];
#pragma unroll
        for (int kk = 0; kk < BK; kk += 8) {
            uint32_t afr[4][4];
#pragma unroll
            for (int mt = 0; mt < 4; mt++) {
                int r = warpM * 64 + mt * 16 + (lane >> 2);
                int c = kk + (lane & 3);
                afr[mt][0] = Ab[r * LDA + c];
                afr[mt][1] = Ab[(r + 8) * LDA + c];
                afr[mt][2] = Ab[r * LDA + c + 4];
                afr[mt][3] = Ab[(r + 8) * LDA + c + 4];
            }
            uint32_t bfr[4][2];
#pragma unroll
            for (int nt = 0; nt < 4; nt++) {
                int cb = warpN * 32 + nt * 8 + (lane >> 2);
                int k  = kk + (lane & 3);
                bfr[nt][0] = Bb[k * LDB + cb];
                bfr[nt][1] = Bb[(k + 4) * LDB + cb];
            }
#pragma unroll
            for (int mt = 0; mt < 4; mt++)
#pragma unroll
                for (int nt = 0; nt < 4; nt++)
                    asm volatile(
                        "mma.sync.aligned.m16n8k8.row.col.f32.tf32.tf32.f32 "
                        "{%0,%1,%2,%3}, {%4,%5,%6,%7}, {%8,%9}, {%0,%1,%2,%3};\n"
                        : "+f"(acc[mt][nt][0]), "+f"(acc[mt][nt][1]),
                          "+f"(acc[mt][nt][2]), "+f"(acc[mt][nt][3])
                        : "r"(afr[mt][0]), "r"(afr[mt][1]), "r"(afr[mt][2]), "r"(afr[mt][3]),
                          "r"(bfr[nt][0]), "r"(bfr[nt][1]));
        }
        __syncthreads();
    }

    // Epilogue: store H_s as fp16
    int s  = n0 >> 8;
    int nl = n0 & 255;
    __half* H = g_h + (size_t)s * NPAD * C;
#pragma unroll
    for (int mt = 0; mt < 4; mt++) {
        int r0 = m0 + warpM * 64 + mt * 16 + (lane >> 2);
#pragma unroll
        for (int nt = 0; nt < 4; nt++) {
            int cc = nl + warpN * 32 + nt * 8 + 2 * (lane & 3);
            if (r0 < n_rows)
                *(__half2*)&H[(size_t)r0 * C + cc] = __floats2half2_rn(acc[mt][nt][0], acc[mt][nt][1]);
            if (r0 + 8 < n_rows)
                *(__half2*)&H[(size_t)(r0 + 8) * C + cc] = __floats2half2_rn(acc[mt][nt][2], acc[mt][nt][3]);
        }
    }
}

// ---------------------------------------------------------------------------
// Aggregation: per node v, batched-prefetch CSR walk, register accumulate,
// one coalesced store. No atomics, no per-edge dependent chains.
// 128 threads/block, 2 channels/thread.
// ---------------------------------------------------------------------------
__global__ __launch_bounds__(128) void agg_kernel(
        const float* __restrict__ x, const float* __restrict__ t0,
        const float* __restrict__ t1, const float* __restrict__ p0,
        const float* __restrict__ p1, float* __restrict__ out) {
    int v = blockIdx.x;
    int c = threadIdx.x * 2;
    float x0 = __ldg(&x[(size_t)v * C]);
    float a0 = x0 * __ldg(&t0[v]);
    float a1 = x0 * __ldg(&t1[v]);
    float accx = a0 * __ldg(&p0[c])     + a1 * __ldg(&p1[c])     + g_bsum[c];
    float accy = a0 * __ldg(&p0[c + 1]) + a1 * __ldg(&p1[c + 1]) + g_bsum[c + 1];

#pragma unroll
    for (int s = 0; s < NSETS; s++) {
        int idx = s * NN + v;
        const __half* Hs = g_h + (size_t)s * NPAD * C;
        float dv = g_dis[idx];
        // self loop: weight = dis[v]^2 = 1/deg (also warms row v in L1 for pad slots)
        {
            float2 f = __half22float2(*(const __half2*)&Hs[(size_t)v * C + c]);
            float w = dv * dv;
            accx += w * f.x;
            accy += w * f.y;
        }
        int off = g_off[idx];
        int ec  = g_deg[idx] - 1;
        for (int j0 = 0; j0 < ec; j0 += 8) {
            int m = ec - j0;
            int   r[8];
            float w[8];
            // Round 1: 16 independent (warp-uniform) index/weight loads
#pragma unroll
            for (int u = 0; u < 8; u++) {
                bool pr = u < m;
                r[u] = pr ? __ldg(&g_rows[off + j0 + u]) : v;
                w[u] = pr ? dv * __ldg(&g_wsrc[off + j0 + u]) : 0.f;
            }
            // Round 2: 8 independent coalesced H gathers
#pragma unroll
            for (int u = 0; u < 8; u++) {
                float2 f = __half22float2(*(const __half2*)&Hs[(size_t)r[u] * C + c]);
                accx += w[u] * f.x;
                accy += w[u] * f.y;
            }
        }
    }
    *(float2*)&out[(size_t)v * C + c] = make_float2(accx, accy);
}

// ---------------------------------------------------------------------------
extern "C" void kernel_launch(void* const* d_in, const int* in_sizes, int n_in,
                              void* d_out, int out_size) {
    const float* x   = (const float*)d_in[0];
    const int* e00   = (const int*)d_in[1];
    const int* e01   = (const int*)d_in[2];
    const int* e10   = (const int*)d_in[3];
    const int* e11   = (const int*)d_in[4];
    const float* t0  = (const float*)d_in[5];
    const float* t1  = (const float*)d_in[6];
    const float* W1  = (const float*)d_in[7];
    const float* b1  = (const float*)d_in[8];
    const float* W2  = (const float*)d_in[9];
    const float* b2  = (const float*)d_in[10];
    const float* W3  = (const float*)d_in[11];
    const float* b3  = (const float*)d_in[12];
    const float* W4  = (const float*)d_in[13];
    const float* b4  = (const float*)d_in[14];
    const float* p0  = (const float*)d_in[15];
    const float* p1  = (const float*)d_in[16];
    const float* p2  = (const float*)d_in[17];
    const float* p3  = (const float*)d_in[18];
    const float* p4  = (const float*)d_in[19];
    const float* p5  = (const float*)d_in[20];

    const int E      = in_sizes[1] / 2;      // 500000
    const int n_rows = in_sizes[0] / C;      // 100000

    cudaFuncSetAttribute(gemm_kernel, cudaFuncAttributeMaxDynamicSharedMemorySize, SMEM_BYTES);

    prep_kernel<<<256, 256>>>(W1, W2, W3, W4, b1, b2, b3, b4, p2, p3, p4, p5);

    int n4 = n_rows * C / 4;
    xcvt_kernel<<<(n4 + 255) / 256, 256>>>(x, n4);

    dim3 dgrid((E + 255) / 256, NSETS);
    deg_kernel<<<dgrid, 256>>>(e00, e01, e10, e11, E);

    dis_kernel<<<(NT + 255) / 256, 256>>>();

    scanA_kernel<<<NBLK, 256>>>();
    scanB_kernel<<<1, 512>>>();
    scanC_kernel<<<NBLK, 256>>>();

    fill_kernel<<<dgrid, 256>>>(e00, e01, e10, e11, E);

    dim3 ggrid((NSETS * C) / BN, (n_rows + BM - 1) / BM);
    gemm_kernel<<<ggrid, 256, SMEM_BYTES>>>(n_rows);

    agg_kernel<<<n_rows, 128>>>(x, t0, t1, p0, p1, (float*)d_out);
}

// round 10
// speedup vs baseline: 1.0668x; 1.0668x over previous
#include <cuda_runtime.h>
#include <cuda_fp16.h>
#include <cstdint>

// Problem constants (fixed instance)
#define NN    100000
#define NPAD  100096          // 782 * 128
#define C     256
#define NSETS 4
#define EMAX  500000
#define NT    (NSETS * NN)    // 400000 (deg/offset table size)
#define NBLK  ((NT + 1023) / 1024)   // 391 scan blocks

// Persistent scratch (device globals — no allocation allowed)
__device__ __half   g_h[(size_t)NSETS * NPAD * C];   // ~205 MB fp16 H_s
__device__ uint32_t g_xtf[(size_t)NPAD * C];         // ~102 MB x pre-converted to tf32 bits
__device__ float    g_dis[NT];                       // rsqrt(deg)
__device__ int      g_deg[NT];                       // 1 + in-edge count
__device__ int      g_off[NT];                       // CSR offsets (global over all sets)
__device__ int      g_cursor[NT];                    // fill cursors
__device__ int      g_rows[NSETS * EMAX];            // CSR: source rows bucketed by (s, col)
__device__ float    g_wsrc[NSETS * EMAX];            // CSR: dis[row] per edge (precomputed)
__device__ int      g_bsums[512];                    // scan block sums
__device__ uint32_t g_wcat[C * (NSETS * C)];         // [256][1024] fused weights, tf32 bits
__device__ float    g_bsum[C];                       // Σ_s b_s ⊙ p_{s+2}

__device__ __forceinline__ uint32_t f2tf32(float f) {
    uint32_t r;
    asm("cvt.rna.tf32.f32 %0, %1;" : "=r"(r) : "f"(f));
    return r;
}

// ---------------------------------------------------------------------------
// Prep: Wcat[k][s*256+n] = tf32(W_s[k][n]*p_{s+2}[n]); bias term; deg init = 1
// ---------------------------------------------------------------------------
__global__ void prep_kernel(const float* __restrict__ W1, const float* __restrict__ W2,
                            const float* __restrict__ W3, const float* __restrict__ W4,
                            const float* __restrict__ b1, const float* __restrict__ b2,
                            const float* __restrict__ b3, const float* __restrict__ b4,
                            const float* __restrict__ p2, const float* __restrict__ p3,
                            const float* __restrict__ p4, const float* __restrict__ p5) {
    int k = blockIdx.x;
    int n = threadIdx.x;
    g_wcat[k * 1024 + 0 * 256 + n] = f2tf32(W1[k * 256 + n] * p2[n]);
    g_wcat[k * 1024 + 1 * 256 + n] = f2tf32(W2[k * 256 + n] * p3[n]);
    g_wcat[k * 1024 + 2 * 256 + n] = f2tf32(W3[k * 256 + n] * p4[n]);
    g_wcat[k * 1024 + 3 * 256 + n] = f2tf32(W4[k * 256 + n] * p5[n]);
    if (k == 0)
        g_bsum[n] = b1[n] * p2[n] + b2[n] * p3[n] + b3[n] * p4[n] + b4[n] * p5[n];
    int idx = k * 256 + n;
    for (int i = idx; i < NT; i += 256 * 256) g_deg[i] = 1;
}

// ---------------------------------------------------------------------------
// x -> tf32 bits (vectorized)
// ---------------------------------------------------------------------------
__global__ void xcvt_kernel(const float* __restrict__ x, int n4) {
    int i = blockIdx.x * blockDim.x + threadIdx.x;
    if (i >= n4) return;
    float4 v = __ldg((const float4*)x + i);
    uint4 o = make_uint4(f2tf32(v.x), f2tf32(v.y), f2tf32(v.z), f2tf32(v.w));
    ((uint4*)g_xtf)[i] = o;
}

// ---------------------------------------------------------------------------
// Degree count
// ---------------------------------------------------------------------------
__global__ void deg_kernel(const int* __restrict__ e0, const int* __restrict__ e1,
                           const int* __restrict__ e2, const int* __restrict__ e3, int E) {
    int s = blockIdx.y;
    int e = blockIdx.x * blockDim.x + threadIdx.x;
    if (e >= E) return;
    const int* eg = (s == 0) ? e0 : (s == 1) ? e1 : (s == 2) ? e2 : e3;
    atomicAdd(&g_deg[s * NN + __ldg(&eg[E + e])], 1);
}

__global__ void dis_kernel() {
    int i = blockIdx.x * blockDim.x + threadIdx.x;
    if (i < NT) g_dis[i] = rsqrtf((float)g_deg[i]);
}

// ---------------------------------------------------------------------------
// Exclusive scan over edge counts (g_deg[i]-1), 3 passes
// ---------------------------------------------------------------------------
__global__ void scanA_kernel() {
    int t = threadIdx.x;
    int base = blockIdx.x * 1024 + t * 4;
    int s = 0;
#pragma unroll
    for (int k = 0; k < 4; k++) {
        int i = base + k;
        if (i < NT) s += g_deg[i] - 1;
    }
    __shared__ int sm[256];
    sm[t] = s;
    __syncthreads();
    for (int d = 128; d > 0; d >>= 1) {
        if (t < d) sm[t] += sm[t + d];
        __syncthreads();
    }
    if (t == 0) g_bsums[blockIdx.x] = sm[0];
}

__global__ void scanB_kernel() {
    int t = threadIdx.x;   // 512 threads
    __shared__ int sm[512];
    int v = (t < NBLK) ? g_bsums[t] : 0;
    sm[t] = v;
    __syncthreads();
    for (int d = 1; d < 512; d <<= 1) {
        int tmp = (t >= d) ? sm[t - d] : 0;
        __syncthreads();
        sm[t] += tmp;
        __syncthreads();
    }
    if (t < NBLK) g_bsums[t] = sm[t] - v;   // exclusive
}

__global__ void scanC_kernel() {
    int t = threadIdx.x;
    int base = blockIdx.x * 1024 + t * 4;
    int a[4], tsum = 0;
#pragma unroll
    for (int k = 0; k < 4; k++) {
        int i = base + k;
        a[k] = (i < NT) ? (g_deg[i] - 1) : 0;
        tsum += a[k];
    }
    __shared__ int sm[256];
    sm[t] = tsum;
    __syncthreads();
    for (int d = 1; d < 256; d <<= 1) {
        int tmp = (t >= d) ? sm[t - d] : 0;
        __syncthreads();
        sm[t] += tmp;
        __syncthreads();
    }
    int run = g_bsums[blockIdx.x] + sm[t] - tsum;
#pragma unroll
    for (int k = 0; k < 4; k++) {
        int i = base + k;
        if (i < NT) {
            g_off[i] = run;
            g_cursor[i] = run;
            run += a[k];
        }
    }
}

// ---------------------------------------------------------------------------
// Bucket edges: g_rows[pos] = source row, g_wsrc[pos] = dis[source]
// ---------------------------------------------------------------------------
__global__ void fill_kernel(const int* __restrict__ e0, const int* __restrict__ e1,
                            const int* __restrict__ e2, const int* __restrict__ e3, int E) {
    int s = blockIdx.y;
    int e = blockIdx.x * blockDim.x + threadIdx.x;
    if (e >= E) return;
    const int* eg = (s == 0) ? e0 : (s == 1) ? e1 : (s == 2) ? e2 : e3;
    int row = __ldg(&eg[e]);
    int col = __ldg(&eg[E + e]);
    int pos = atomicAdd(&g_cursor[s * NN + col], 1);
    g_rows[pos] = row;
    g_wsrc[pos] = g_dis[s * NN + row];
}

// ---------------------------------------------------------------------------
// tf32 GEMM: H[s][v][n] = sum_k x[v][k] * Wcat[k][s*256+n], fp16 output
// ---------------------------------------------------------------------------
#define BM 128
#define BN 128
#define BK 32
#define LDA 36
#define LDB 136

static constexpr int SMEM_BYTES = (2 * BM * LDA + 2 * BK * LDB) * 4;  // 71680

__device__ __forceinline__ void cp_async16(uint32_t* smem_ptr, const uint32_t* gmem_ptr, int src_bytes) {
    uint32_t saddr = (uint32_t)__cvta_generic_to_shared(smem_ptr);
    asm volatile("cp.async.cg.shared.global [%0], [%1], 16, %2;\n"
                 :: "r"(saddr), "l"(gmem_ptr), "r"(src_bytes));
}

__global__ __launch_bounds__(256, 2) void gemm_kernel(int n_rows) {
    extern __shared__ uint32_t sm[];
    uint32_t* Asm[2] = { sm, sm + BM * LDA };
    uint32_t* Bsm[2] = { sm + 2 * BM * LDA, sm + 2 * BM * LDA + BK * LDB };

    const int tid   = threadIdx.x;
    const int lane  = tid & 31;
    const int warp  = tid >> 5;
    const int warpM = warp >> 2;   // 0..1
    const int warpN = warp & 3;    // 0..3
    const int m0 = blockIdx.y * BM;
    const int n0 = blockIdx.x * BN;

    float acc[4][4][4];
#pragma unroll
    for (int i = 0; i < 4; i++)
#pragma unroll
        for (int j = 0; j < 4; j++)
#pragma unroll
            for (int k = 0; k < 4; k++) acc[i][j][k] = 0.f;

    auto loadA = [&](int buf, int kb) {
#pragma unroll
        for (int p = 0; p < 4; p++) {
            int idx = tid + p * 256;
            int row = idx >> 3;
            int c4  = idx & 7;
            int gr  = m0 + row;
            const uint32_t* src = g_xtf + (size_t)gr * C + kb + c4 * 4;
            cp_async16(&Asm[buf][row * LDA + c4 * 4], src, gr < n_rows ? 16 : 0);
        }
    };
    auto loadB = [&](int buf, int kb) {
#pragma unroll
        for (int p = 0; p < 4; p++) {
            int idx = tid + p * 256;
            int row = idx >> 5;
            int c4  = idx & 31;
            const uint32_t* src = g_wcat + (size_t)(kb + row) * 1024 + n0 + c4 * 4;
            cp_async16(&Bsm[buf][row * LDB + c4 * 4], src, 16);
        }
    };

    loadA(0, 0); loadB(0, 0);
    asm volatile("cp.async.commit_group;\n");

#pragma unroll 1
    for (int kc = 0; kc < 8; kc++) {          // K = 256 = 8 * BK
        int cur = kc & 1;
        if (kc < 7) {
            loadA(cur ^ 1, (kc + 1) * BK);
            loadB(cur ^ 1, (kc + 1) * BK);
            asm volatile("cp.async.commit_group;\n");
            asm volatile("cp.async.wait_group 1;\n");
        } else {
            asm volatile("cp.async.wait_group 0;\n");
        }
        __syncthreads();

        const uint32_t* Ab = Asm[cur];
        const uint32_t* Bb = Bsm[cur];
#pragma unroll
        for (int kk = 0; kk < BK; kk += 8) {
            uint32_t afr[4][4];
#pragma unroll
            for (int mt = 0; mt < 4; mt++) {
                int r = warpM * 64 + mt * 16 + (lane >> 2);
                int c = kk + (lane & 3);
                afr[mt][0] = Ab[r * LDA + c];
                afr[mt][1] = Ab[(r + 8) * LDA + c];
                afr[mt][2] = Ab[r * LDA + c + 4];
                afr[mt][3] = Ab[(r + 8) * LDA + c + 4];
            }
            uint32_t bfr[4][2];
#pragma unroll
            for (int nt = 0; nt < 4; nt++) {
                int cb = warpN * 32 + nt * 8 + (lane >> 2);
                int k  = kk + (lane & 3);
                bfr[nt][0] = Bb[k * LDB + cb];
                bfr[nt][1] = Bb[(k + 4) * LDB + cb];
            }
#pragma unroll
            for (int mt = 0; mt < 4; mt++)
#pragma unroll
                for (int nt = 0; nt < 4; nt++)
                    asm volatile(
                        "mma.sync.aligned.m16n8k8.row.col.f32.tf32.tf32.f32 "
                        "{%0,%1,%2,%3}, {%4,%5,%6,%7}, {%8,%9}, {%0,%1,%2,%3};\n"
                        : "+f"(acc[mt][nt][0]), "+f"(acc[mt][nt][1]),
                          "+f"(acc[mt][nt][2]), "+f"(acc[mt][nt][3])
                        : "r"(afr[mt][0]), "r"(afr[mt][1]), "r"(afr[mt][2]), "r"(afr[mt][3]),
                          "r"(bfr[nt][0]), "r"(bfr[nt][1]));
        }
        __syncthreads();
    }

    // Epilogue: store H_s as fp16
    int s  = n0 >> 8;
    int nl = n0 & 255;
    __half* H = g_h + (size_t)s * NPAD * C;
#pragma unroll
    for (int mt = 0; mt < 4; mt++) {
        int r0 = m0 + warpM * 64 + mt * 16 + (lane >> 2);
#pragma unroll
        for (int nt = 0; nt < 4; nt++) {
            int cc = nl + warpN * 32 + nt * 8 + 2 * (lane & 3);
            if (r0 < n_rows)
                *(__half2*)&H[(size_t)r0 * C + cc] = __floats2half2_rn(acc[mt][nt][0], acc[mt][nt][1]);
            if (r0 + 8 < n_rows)
                *(__half2*)&H[(size_t)(r0 + 8) * C + cc] = __floats2half2_rn(acc[mt][nt][2], acc[mt][nt][3]);
        }
    }
}

// ---------------------------------------------------------------------------
// Aggregation with shared-memory CSR staging: indices/weights loaded ONCE per
// block (coalesced), broadcast via smem; gathers issued 4-deep independent.
// 128 threads/block, 2 channels/thread. No atomics.
// ---------------------------------------------------------------------------
__global__ __launch_bounds__(128) void agg_kernel(
        const float* __restrict__ x, const float* __restrict__ t0,
        const float* __restrict__ t1, const float* __restrict__ p0,
        const float* __restrict__ p1, float* __restrict__ out) {
    __shared__ int   sr[128];
    __shared__ float swt[128];

    int v = blockIdx.x;
    int tid = threadIdx.x;
    int c = tid * 2;
    float x0 = __ldg(&x[(size_t)v * C]);
    float a0 = x0 * __ldg(&t0[v]);
    float a1 = x0 * __ldg(&t1[v]);
    float accx = a0 * __ldg(&p0[c])     + a1 * __ldg(&p1[c])     + g_bsum[c];
    float accy = a0 * __ldg(&p0[c + 1]) + a1 * __ldg(&p1[c + 1]) + g_bsum[c + 1];

#pragma unroll
    for (int s = 0; s < NSETS; s++) {
        int idx = s * NN + v;
        const __half* Hs = g_h + (size_t)s * NPAD * C;
        float dv = g_dis[idx];
        // self loop: weight = dis[v]^2 = 1/deg
        {
            float2 f = __half22float2(*(const __half2*)&Hs[(size_t)v * C + c]);
            float w = dv * dv;
            accx += w * f.x;
            accy += w * f.y;
        }
        int off = g_off[idx];
        int ec  = g_deg[idx] - 1;
        for (int b0 = 0; b0 < ec; b0 += 128) {
            int cnt = min(128, ec - b0);
            __syncthreads();
            if (tid < cnt) {
                sr[tid]  = __ldg(&g_rows[off + b0 + tid]);
                swt[tid] = dv * __ldg(&g_wsrc[off + b0 + tid]);
            }
            __syncthreads();
            int j = 0;
            for (; j + 4 <= cnt; j += 4) {
                int   r0 = sr[j],     r1 = sr[j + 1], r2 = sr[j + 2], r3 = sr[j + 3];
                float w0 = swt[j],    w1 = swt[j + 1], w2 = swt[j + 2], w3 = swt[j + 3];
                float2 f0 = __half22float2(*(const __half2*)&Hs[(size_t)r0 * C + c]);
                float2 f1 = __half22float2(*(const __half2*)&Hs[(size_t)r1 * C + c]);
                float2 f2 = __half22float2(*(const __half2*)&Hs[(size_t)r2 * C + c]);
                float2 f3 = __half22float2(*(const __half2*)&Hs[(size_t)r3 * C + c]);
                accx += w0 * f0.x + w1 * f1.x + w2 * f2.x + w3 * f3.x;
                accy += w0 * f0.y + w1 * f1.y + w2 * f2.y + w3 * f3.y;
            }
            for (; j < cnt; j++) {
                int   r0 = sr[j];
                float w0 = swt[j];
                float2 f0 = __half22float2(*(const __half2*)&Hs[(size_t)r0 * C + c]);
                accx += w0 * f0.x;
                accy += w0 * f0.y;
            }
        }
    }
    *(float2*)&out[(size_t)v * C + c] = make_float2(accx, accy);
}

// ---------------------------------------------------------------------------
extern "C" void kernel_launch(void* const* d_in, const int* in_sizes, int n_in,
                              void* d_out, int out_size) {
    const float* x   = (const float*)d_in[0];
    const int* e00   = (const int*)d_in[1];
    const int* e01   = (const int*)d_in[2];
    const int* e10   = (const int*)d_in[3];
    const int* e11   = (const int*)d_in[4];
    const float* t0  = (const float*)d_in[5];
    const float* t1  = (const float*)d_in[6];
    const float* W1  = (const float*)d_in[7];
    const float* b1  = (const float*)d_in[8];
    const float* W2  = (const float*)d_in[9];
    const float* b2  = (const float*)d_in[10];
    const float* W3  = (const float*)d_in[11];
    const float* b3  = (const float*)d_in[12];
    const float* W4  = (const float*)d_in[13];
    const float* b4  = (const float*)d_in[14];
    const float* p0  = (const float*)d_in[15];
    const float* p1  = (const float*)d_in[16];
    const float* p2  = (const float*)d_in[17];
    const float* p3  = (const float*)d_in[18];
    const float* p4  = (const float*)d_in[19];
    const float* p5  = (const float*)d_in[20];

    const int E      = in_sizes[1] / 2;      // 500000
    const int n_rows = in_sizes[0] / C;      // 100000

    cudaFuncSetAttribute(gemm_kernel, cudaFuncAttributeMaxDynamicSharedMemorySize, SMEM_BYTES);

    prep_kernel<<<256, 256>>>(W1, W2, W3, W4, b1, b2, b3, b4, p2, p3, p4, p5);

    int n4 = n_rows * C / 4;
    xcvt_kernel<<<(n4 + 255) / 256, 256>>>(x, n4);

    dim3 dgrid((E + 255) / 256, NSETS);
    deg_kernel<<<dgrid, 256>>>(e00, e01, e10, e11, E);

    dis_kernel<<<(NT + 255) / 256, 256>>>();

    scanA_kernel<<<NBLK, 256>>>();
    scanB_kernel<<<1, 512>>>();
    scanC_kernel<<<NBLK, 256>>>();

    fill_kernel<<<dgrid, 256>>>(e00, e01, e10, e11, E);

    dim3 ggrid((NSETS * C) / BN, (n_rows + BM - 1) / BM);
    gemm_kernel<<<ggrid, 256, SMEM_BYTES>>>(n_rows);

    agg_kernel<<<n_rows, 128>>>(x, t0, t1, p0, p1, (float*)d_out);
}

// round 11
// speedup vs baseline: 1.2953x; 1.2142x over previous
#include <cuda_runtime.h>
#include <cuda_fp16.h>
#include <cstdint>

// Problem constants (fixed instance)
#define NN    100000
#define NPAD  100096          // 782 * 128
#define C     256
#define NSETS 4
#define EMAX  500000
#define NT    (NSETS * NN)    // 400000
#define MCAP  (NSETS * (EMAX + NN))   // 2.4M merged entries
#define NBLK2 ((NN + 1023) / 1024)    // 98 scan blocks over nodes

// Persistent scratch (device globals — no allocation allowed)
__device__ __half   g_h[(size_t)NSETS * NPAD * C];   // ~205 MB fp16 H arena (flat rows)
__device__ uint32_t g_xtf[(size_t)NPAD * C];         // ~102 MB x as tf32 bits
__device__ float    g_dis[NT];                       // rsqrt(deg)
__device__ int      g_deg[NT];                       // 1 + in-edge count
__device__ int      g_moff[NN];                      // merged CSR offsets (per node)
__device__ int      g_mcnt[NN];                      // merged counts
__device__ int      g_mcur[NN];                      // fill cursors
__device__ int      g_mrow[MCAP];                    // flat H row index (s*NPAD + row)
__device__ float    g_mw[MCAP];                      // fully precomputed edge weight
__device__ int      g_bsums[256];                    // scan block sums
__device__ uint32_t g_wcat[C * (NSETS * C)];         // [256][1024] fused weights, tf32 bits
__device__ float    g_bsum[C];                       // Σ_s b_s ⊙ p_{s+2}

__device__ __forceinline__ uint32_t f2tf32(float f) {
    uint32_t r;
    asm("cvt.rna.tf32.f32 %0, %1;" : "=r"(r) : "f"(f));
    return r;
}

// ---------------------------------------------------------------------------
// Prep: Wcat[k][s*256+n] = tf32(W_s[k][n]*p_{s+2}[n]); bias term; deg init = 1
// ---------------------------------------------------------------------------
__global__ void prep_kernel(const float* __restrict__ W1, const float* __restrict__ W2,
                            const float* __restrict__ W3, const float* __restrict__ W4,
                            const float* __restrict__ b1, const float* __restrict__ b2,
                            const float* __restrict__ b3, const float* __restrict__ b4,
                            const float* __restrict__ p2, const float* __restrict__ p3,
                            const float* __restrict__ p4, const float* __restrict__ p5) {
    int k = blockIdx.x;
    int n = threadIdx.x;
    g_wcat[k * 1024 + 0 * 256 + n] = f2tf32(W1[k * 256 + n] * p2[n]);
    g_wcat[k * 1024 + 1 * 256 + n] = f2tf32(W2[k * 256 + n] * p3[n]);
    g_wcat[k * 1024 + 2 * 256 + n] = f2tf32(W3[k * 256 + n] * p4[n]);
    g_wcat[k * 1024 + 3 * 256 + n] = f2tf32(W4[k * 256 + n] * p5[n]);
    if (k == 0)
        g_bsum[n] = b1[n] * p2[n] + b2[n] * p3[n] + b3[n] * p4[n] + b4[n] * p5[n];
    int idx = k * 256 + n;
    for (int i = idx; i < NT; i += 256 * 256) g_deg[i] = 1;
}

// ---------------------------------------------------------------------------
// x -> tf32 bits (vectorized)
// ---------------------------------------------------------------------------
__global__ void xcvt_kernel(const float* __restrict__ x, int n4) {
    int i = blockIdx.x * blockDim.x + threadIdx.x;
    if (i >= n4) return;
    float4 v = __ldg((const float4*)x + i);
    uint4 o = make_uint4(f2tf32(v.x), f2tf32(v.y), f2tf32(v.z), f2tf32(v.w));
    ((uint4*)g_xtf)[i] = o;
}

// ---------------------------------------------------------------------------
// Degree count
// ---------------------------------------------------------------------------
__global__ void deg_kernel(const int* __restrict__ e0, const int* __restrict__ e1,
                           const int* __restrict__ e2, const int* __restrict__ e3, int E) {
    int s = blockIdx.y;
    int e = blockIdx.x * blockDim.x + threadIdx.x;
    if (e >= E) return;
    const int* eg = (s == 0) ? e0 : (s == 1) ? e1 : (s == 2) ? e2 : e3;
    atomicAdd(&g_deg[s * NN + __ldg(&eg[E + e])], 1);
}

__global__ void dis_kernel() {
    int i = blockIdx.x * blockDim.x + threadIdx.x;
    if (i < NT) g_dis[i] = rsqrtf((float)g_deg[i]);
}

// ---------------------------------------------------------------------------
// Exclusive scan over merged per-node counts: cnt(v) = Σ_s deg[s,v]
// (deg = 1 + edges, so this includes the 4 self-loop slots)
// ---------------------------------------------------------------------------
__device__ __forceinline__ int node_count(int v) {
    return g_deg[v] + g_deg[NN + v] + g_deg[2 * NN + v] + g_deg[3 * NN + v];
}

__global__ void mscanA_kernel() {
    int t = threadIdx.x;
    int base = blockIdx.x * 1024 + t * 4;
    int s = 0;
#pragma unroll
    for (int k = 0; k < 4; k++) {
        int v = base + k;
        if (v < NN) s += node_count(v);
    }
    __shared__ int sm[256];
    sm[t] = s;
    __syncthreads();
    for (int d = 128; d > 0; d >>= 1) {
        if (t < d) sm[t] += sm[t + d];
        __syncthreads();
    }
    if (t == 0) g_bsums[blockIdx.x] = sm[0];
}

__global__ void mscanB_kernel() {
    int t = threadIdx.x;   // 128 threads >= NBLK2 (98)
    __shared__ int sm[128];
    int v = (t < NBLK2) ? g_bsums[t] : 0;
    sm[t] = v;
    __syncthreads();
    for (int d = 1; d < 128; d <<= 1) {
        int tmp = (t >= d) ? sm[t - d] : 0;
        __syncthreads();
        sm[t] += tmp;
        __syncthreads();
    }
    if (t < NBLK2) g_bsums[t] = sm[t] - v;   // exclusive
}

__global__ void mscanC_kernel() {
    int t = threadIdx.x;
    int base = blockIdx.x * 1024 + t * 4;
    int a[4], tsum = 0;
#pragma unroll
    for (int k = 0; k < 4; k++) {
        int v = base + k;
        a[k] = (v < NN) ? node_count(v) : 0;
        tsum += a[k];
    }
    __shared__ int sm[256];
    sm[t] = tsum;
    __syncthreads();
    for (int d = 1; d < 256; d <<= 1) {
        int tmp = (t >= d) ? sm[t - d] : 0;
        __syncthreads();
        sm[t] += tmp;
        __syncthreads();
    }
    int run = g_bsums[blockIdx.x] + sm[t] - tsum;
#pragma unroll
    for (int k = 0; k < 4; k++) {
        int v = base + k;
        if (v < NN) {
            g_moff[v] = run;
            g_mcnt[v] = a[k];
            g_mcur[v] = run;
            run += a[k];
        }
    }
}

// ---------------------------------------------------------------------------
// Fill self-loop entries: weight = dis^2 = 1/deg, flat row = s*NPAD + v
// ---------------------------------------------------------------------------
__global__ void fillself_kernel() {
    int v = blockIdx.x * blockDim.x + threadIdx.x;
    if (v >= NN) return;
#pragma unroll
    for (int s = 0; s < NSETS; s++) {
        int pos = atomicAdd(&g_mcur[v], 1);
        float d = g_dis[s * NN + v];
        g_mrow[pos] = s * NPAD + v;
        g_mw[pos]   = d * d;
    }
}

// ---------------------------------------------------------------------------
// Fill edge entries: weight = dis[s,col]*dis[s,row], flat row = s*NPAD + row
// ---------------------------------------------------------------------------
__global__ void filledge_kernel(const int* __restrict__ e0, const int* __restrict__ e1,
                                const int* __restrict__ e2, const int* __restrict__ e3, int E) {
    int s = blockIdx.y;
    int e = blockIdx.x * blockDim.x + threadIdx.x;
    if (e >= E) return;
    const int* eg = (s == 0) ? e0 : (s == 1) ? e1 : (s == 2) ? e2 : e3;
    int row = __ldg(&eg[e]);
    int col = __ldg(&eg[E + e]);
    int pos = atomicAdd(&g_mcur[col], 1);
    g_mrow[pos] = s * NPAD + row;
    g_mw[pos]   = g_dis[s * NN + col] * g_dis[s * NN + row];
}

// ---------------------------------------------------------------------------
// tf32 GEMM: H[s][v][n] = sum_k x[v][k] * Wcat[k][s*256+n], fp16 output
// ---------------------------------------------------------------------------
#define BM 128
#define BN 128
#define BK 32
#define LDA 36
#define LDB 136

static constexpr int SMEM_BYTES = (2 * BM * LDA + 2 * BK * LDB) * 4;  // 71680

__device__ __forceinline__ void cp_async16(uint32_t* smem_ptr, const uint32_t* gmem_ptr, int src_bytes) {
    uint32_t saddr = (uint32_t)__cvta_generic_to_shared(smem_ptr);
    asm volatile("cp.async.cg.shared.global [%0], [%1], 16, %2;\n"
                 :: "r"(saddr), "l"(gmem_ptr), "r"(src_bytes));
}

__global__ __launch_bounds__(256, 2) void gemm_kernel(int n_rows) {
    extern __shared__ uint32_t sm[];
    uint32_t* Asm[2] = { sm, sm + BM * LDA };
    uint32_t* Bsm[2] = { sm + 2 * BM * LDA, sm + 2 * BM * LDA + BK * LDB };

    const int tid   = threadIdx.x;
    const int lane  = tid & 31;
    const int warp  = tid >> 5;
    const int warpM = warp >> 2;   // 0..1
    const int warpN = warp & 3;    // 0..3
    const int m0 = blockIdx.y * BM;
    const int n0 = blockIdx.x * BN;

    float acc[4][4][4];
#pragma unroll
    for (int i = 0; i < 4; i++)
#pragma unroll
        for (int j = 0; j < 4; j++)
#pragma unroll
            for (int k = 0; k < 4; k++) acc[i][j][k] = 0.f;

    auto loadA = [&](int buf, int kb) {
#pragma unroll
        for (int p = 0; p < 4; p++) {
            int idx = tid + p * 256;
            int row = idx >> 3;
            int c4  = idx & 7;
            int gr  = m0 + row;
            const uint32_t* src = g_xtf + (size_t)gr * C + kb + c4 * 4;
            cp_async16(&Asm[buf][row * LDA + c4 * 4], src, gr < n_rows ? 16 : 0);
        }
    };
    auto loadB = [&](int buf, int kb) {
#pragma unroll
        for (int p = 0; p < 4; p++) {
            int idx = tid + p * 256;
            int row = idx >> 5;
            int c4  = idx & 31;
            const uint32_t* src = g_wcat + (size_t)(kb + row) * 1024 + n0 + c4 * 4;
            cp_async16(&Bsm[buf][row * LDB + c4 * 4], src, 16);
        }
    };

    loadA(0, 0); loadB(0, 0);
    asm volatile("cp.async.commit_group;\n");

#pragma unroll 1
    for (int kc = 0; kc < 8; kc++) {          // K = 256 = 8 * BK
        int cur = kc & 1;
        if (kc < 7) {
            loadA(cur ^ 1, (kc + 1) * BK);
            loadB(cur ^ 1, (kc + 1) * BK);
            asm volatile("cp.async.commit_group;\n");
            asm volatile("cp.async.wait_group 1;\n");
        } else {
            asm volatile("cp.async.wait_group 0;\n");
        }
        __syncthreads();

        const uint32_t* Ab = Asm[cur];
        const uint32_t* Bb = Bsm[cur];
#pragma unroll
        for (int kk = 0; kk < BK; kk += 8) {
            uint32_t afr[4][4];
#pragma unroll
            for (int mt = 0; mt < 4; mt++) {
                int r = warpM * 64 + mt * 16 + (lane >> 2);
                int c = kk + (lane & 3);
                afr[mt][0] = Ab[r * LDA + c];
                afr[mt][1] = Ab[(r + 8) * LDA + c];
                afr[mt][2] = Ab[r * LDA + c + 4];
                afr[mt][3] = Ab[(r + 8) * LDA + c + 4];
            }
            uint32_t bfr[4][2];
#pragma unroll
            for (int nt = 0; nt < 4; nt++) {
                int cb = warpN * 32 + nt * 8 + (lane >> 2);
                int k  = kk + (lane & 3);
                bfr[nt][0] = Bb[k * LDB + cb];
                bfr[nt][1] = Bb[(k + 4) * LDB + cb];
            }
#pragma unroll
            for (int mt = 0; mt < 4; mt++)
#pragma unroll
                for (int nt = 0; nt < 4; nt++)
                    asm volatile(
                        "mma.sync.aligned.m16n8k8.row.col.f32.tf32.tf32.f32 "
                        "{%0,%1,%2,%3}, {%4,%5,%6,%7}, {%8,%9}, {%0,%1,%2,%3};\n"
                        : "+f"(acc[mt][nt][0]), "+f"(acc[mt][nt][1]),
                          "+f"(acc[mt][nt][2]), "+f"(acc[mt][nt][3])
                        : "r"(afr[mt][0]), "r"(afr[mt][1]), "r"(afr[mt][2]), "r"(afr[mt][3]),
                          "r"(bfr[nt][0]), "r"(bfr[nt][1]));
        }
        __syncthreads();
    }

    // Epilogue: store H_s as fp16
    int s  = n0 >> 8;
    int nl = n0 & 255;
    __half* H = g_h + (size_t)s * NPAD * C;
#pragma unroll
    for (int mt = 0; mt < 4; mt++) {
        int r0 = m0 + warpM * 64 + mt * 16 + (lane >> 2);
#pragma unroll
        for (int nt = 0; nt < 4; nt++) {
            int cc = nl + warpN * 32 + nt * 8 + 2 * (lane & 3);
            if (r0 < n_rows)
                *(__half2*)&H[(size_t)r0 * C + cc] = __floats2half2_rn(acc[mt][nt][0], acc[mt][nt][1]);
            if (r0 + 8 < n_rows)
                *(__half2*)&H[(size_t)(r0 + 8) * C + cc] = __floats2half2_rn(acc[mt][nt][2], acc[mt][nt][3]);
        }
    }
}

// ---------------------------------------------------------------------------
// Aggregation over the MERGED per-node list (self-loops + all 4 edge sets,
// weights fully precomputed). One staging pass, two syncs, 4-deep gathers.
// 128 threads/block, 2 channels/thread. No atomics.
// ---------------------------------------------------------------------------
__global__ __launch_bounds__(128) void agg_kernel(
        const float* __restrict__ x, const float* __restrict__ t0,
        const float* __restrict__ t1, const float* __restrict__ p0,
        const float* __restrict__ p1, float* __restrict__ out) {
    __shared__ int   sr[256];
    __shared__ float sw[256];

    int v = blockIdx.x;
    int tid = threadIdx.x;
    int c = tid * 2;
    float x0 = __ldg(&x[(size_t)v * C]);
    float a0 = x0 * __ldg(&t0[v]);
    float a1 = x0 * __ldg(&t1[v]);
    float accx = a0 * __ldg(&p0[c])     + a1 * __ldg(&p1[c])     + g_bsum[c];
    float accy = a0 * __ldg(&p0[c + 1]) + a1 * __ldg(&p1[c + 1]) + g_bsum[c + 1];

    const int off = g_moff[v];
    const int cnt = g_mcnt[v];

    for (int b0 = 0; b0 < cnt; b0 += 256) {
        int k = min(256, cnt - b0);
        __syncthreads();
        if (tid < k) {
            sr[tid] = __ldg(&g_mrow[off + b0 + tid]);
            sw[tid] = __ldg(&g_mw[off + b0 + tid]);
        }
        if (tid + 128 < k) {
            sr[tid + 128] = __ldg(&g_mrow[off + b0 + tid + 128]);
            sw[tid + 128] = __ldg(&g_mw[off + b0 + tid + 128]);
        }
        __syncthreads();
        int j = 0;
        for (; j + 4 <= k; j += 4) {
            int   r0 = sr[j],  r1 = sr[j + 1], r2 = sr[j + 2], r3 = sr[j + 3];
            float w0 = sw[j],  w1 = sw[j + 1], w2 = sw[j + 2], w3 = sw[j + 3];
            float2 f0 = __half22float2(*(const __half2*)&g_h[(size_t)r0 * C + c]);
            float2 f1 = __half22float2(*(const __half2*)&g_h[(size_t)r1 * C + c]);
            float2 f2 = __half22float2(*(const __half2*)&g_h[(size_t)r2 * C + c]);
            float2 f3 = __half22float2(*(const __half2*)&g_h[(size_t)r3 * C + c]);
            accx += w0 * f0.x + w1 * f1.x + w2 * f2.x + w3 * f3.x;
            accy += w0 * f0.y + w1 * f1.y + w2 * f2.y + w3 * f3.y;
        }
        for (; j < k; j++) {
            int   r0 = sr[j];
            float w0 = sw[j];
            float2 f0 = __half22float2(*(const __half2*)&g_h[(size_t)r0 * C + c]);
            accx += w0 * f0.x;
            accy += w0 * f0.y;
        }
    }
    *(float2*)&out[(size_t)v * C + c] = make_float2(accx, accy);
}

// ---------------------------------------------------------------------------
extern "C" void kernel_launch(void* const* d_in, const int* in_sizes, int n_in,
                              void* d_out, int out_size) {
    const float* x   = (const float*)d_in[0];
    const int* e00   = (const int*)d_in[1];
    const int* e01   = (const int*)d_in[2];
    const int* e10   = (const int*)d_in[3];
    const int* e11   = (const int*)d_in[4];
    const float* t0  = (const float*)d_in[5];
    const float* t1  = (const float*)d_in[6];
    const float* W1  = (const float*)d_in[7];
    const float* b1  = (const float*)d_in[8];
    const float* W2  = (const float*)d_in[9];
    const float* b2  = (const float*)d_in[10];
    const float* W3  = (const float*)d_in[11];
    const float* b3  = (const float*)d_in[12];
    const float* W4  = (const float*)d_in[13];
    const float* b4  = (const float*)d_in[14];
    const float* p0  = (const float*)d_in[15];
    const float* p1  = (const float*)d_in[16];
    const float* p2  = (const float*)d_in[17];
    const float* p3  = (const float*)d_in[18];
    const float* p4  = (const float*)d_in[19];
    const float* p5  = (const float*)d_in[20];

    const int E      = in_sizes[1] / 2;      // 500000
    const int n_rows = in_sizes[0] / C;      // 100000

    cudaFuncSetAttribute(gemm_kernel, cudaFuncAttributeMaxDynamicSharedMemorySize, SMEM_BYTES);

    prep_kernel<<<256, 256>>>(W1, W2, W3, W4, b1, b2, b3, b4, p2, p3, p4, p5);

    int n4 = n_rows * C / 4;
    xcvt_kernel<<<(n4 + 255) / 256, 256>>>(x, n4);

    dim3 dgrid((E + 255) / 256, NSETS);
    deg_kernel<<<dgrid, 256>>>(e00, e01, e10, e11, E);

    dis_kernel<<<(NT + 255) / 256, 256>>>();

    mscanA_kernel<<<NBLK2, 256>>>();
    mscanB_kernel<<<1, 128>>>();
    mscanC_kernel<<<NBLK2, 256>>>();

    fillself_kernel<<<(NN + 255) / 256, 256>>>();
    filledge_kernel<<<dgrid, 256>>>(e00, e01, e10, e11, E);

    dim3 ggrid((NSETS * C) / BN, (n_rows + BM - 1) / BM);
    gemm_kernel<<<ggrid, 256, SMEM_BYTES>>>(n_rows);

    agg_kernel<<<n_rows, 128>>>(x, t0, t1, p0, p1, (float*)d_out);
}

// round 14
// speedup vs baseline: 1.5864x; 1.2248x over previous
#include <cuda_runtime.h>
#include <cuda_fp16.h>
#include <cstdint>

// Problem constants (fixed instance)
#define NN    100000
#define NPAD  100096          // 782 * 128
#define C     256
#define NSETS 4
#define EMAX  500000
#define NT    (NSETS * NN)    // 400000
#define MCAP  (NSETS * (EMAX + NN))   // 2.4M merged entries
#define NBLK2 ((NN + 1023) / 1024)    // 98 scan blocks over nodes

// Persistent scratch (device globals — no allocation allowed)
__device__ __half   g_h[(size_t)NSETS * NPAD * C];   // ~205 MB fp16 H arena (flat rows)
__device__ __half   g_xh[(size_t)NPAD * C];          // ~51 MB x as fp16
__device__ float    g_dis[NT];                       // rsqrt(deg)
__device__ int      g_deg[NT];                       // 1 + in-edge count
__device__ int      g_moff[NN];                      // merged CSR offsets
__device__ int      g_mcnt[NN];                      // merged counts
__device__ int      g_mcur[NN];                      // fill cursors
__device__ int      g_mrow[MCAP];                    // flat H row index (s*NPAD + row)
__device__ float    g_mw[MCAP];                      // fully precomputed edge weight
__device__ int      g_bsums[256];                    // scan block sums
__device__ __half   g_wh[(NSETS * C) * C];           // [1024][256] fused weights, fp16, K-major
__device__ float    g_bsum[C];                       // Σ_s b_s ⊙ p_{s+2}

// ---------------------------------------------------------------------------
// Prep: g_wh[(s*256+n)][k] = half(W_s[k][n]*p_{s+2}[n]); bias; deg init = 1
// ---------------------------------------------------------------------------
__global__ void prep_kernel(const float* __restrict__ W1, const float* __restrict__ W2,
                            const float* __restrict__ W3, const float* __restrict__ W4,
                            const float* __restrict__ b1, const float* __restrict__ b2,
                            const float* __restrict__ b3, const float* __restrict__ b4,
                            const float* __restrict__ p2, const float* __restrict__ p3,
                            const float* __restrict__ p4, const float* __restrict__ p5) {
    int k = blockIdx.x;
    int n = threadIdx.x;
    g_wh[(size_t)(0 * 256 + n) * 256 + k] = __float2half_rn(W1[k * 256 + n] * p2[n]);
    g_wh[(size_t)(1 * 256 + n) * 256 + k] = __float2half_rn(W2[k * 256 + n] * p3[n]);
    g_wh[(size_t)(2 * 256 + n) * 256 + k] = __float2half_rn(W3[k * 256 + n] * p4[n]);
    g_wh[(size_t)(3 * 256 + n) * 256 + k] = __float2half_rn(W4[k * 256 + n] * p5[n]);
    if (k == 0)
        g_bsum[n] = b1[n] * p2[n] + b2[n] * p3[n] + b3[n] * p4[n] + b4[n] * p5[n];
    int idx = k * 256 + n;
    for (int i = idx; i < NT; i += 256 * 256) g_deg[i] = 1;
}

// ---------------------------------------------------------------------------
// x -> fp16 (vectorized: 4 floats -> 4 halves per thread)
// ---------------------------------------------------------------------------
__global__ void xcvt_kernel(const float* __restrict__ x, int n4) {
    int i = blockIdx.x * blockDim.x + threadIdx.x;
    if (i >= n4) return;
    float4 v = __ldg((const float4*)x + i);
    __half2 h0 = __floats2half2_rn(v.x, v.y);
    __half2 h1 = __floats2half2_rn(v.z, v.w);
    uint2 o;
    o.x = *(const uint32_t*)&h0;
    o.y = *(const uint32_t*)&h1;
    ((uint2*)g_xh)[i] = o;
}

// ---------------------------------------------------------------------------
// Degree count
// ---------------------------------------------------------------------------
__global__ void deg_kernel(const int* __restrict__ e0, const int* __restrict__ e1,
                           const int* __restrict__ e2, const int* __restrict__ e3, int E) {
    int s = blockIdx.y;
    int e = blockIdx.x * blockDim.x + threadIdx.x;
    if (e >= E) return;
    const int* eg = (s == 0) ? e0 : (s == 1) ? e1 : (s == 2) ? e2 : e3;
    atomicAdd(&g_deg[s * NN + __ldg(&eg[E + e])], 1);
}

__global__ void dis_kernel() {
    int i = blockIdx.x * blockDim.x + threadIdx.x;
    if (i < NT) g_dis[i] = rsqrtf((float)g_deg[i]);
}

// ---------------------------------------------------------------------------
// Exclusive scan over merged per-node counts: cnt(v) = Σ_s deg[s,v]
// ---------------------------------------------------------------------------
__device__ __forceinline__ int node_count(int v) {
    return g_deg[v] + g_deg[NN + v] + g_deg[2 * NN + v] + g_deg[3 * NN + v];
}

__global__ void mscanA_kernel() {
    int t = threadIdx.x;
    int base = blockIdx.x * 1024 + t * 4;
    int s = 0;
#pragma unroll
    for (int k = 0; k < 4; k++) {
        int v = base + k;
        if (v < NN) s += node_count(v);
    }
    __shared__ int sm[256];
    sm[t] = s;
    __syncthreads();
    for (int d = 128; d > 0; d >>= 1) {
        if (t < d) sm[t] += sm[t + d];
        __syncthreads();
    }
    if (t == 0) g_bsums[blockIdx.x] = sm[0];
}

__global__ void mscanB_kernel() {
    int t = threadIdx.x;   // 128 threads >= NBLK2 (98)
    __shared__ int sm[128];
    int v = (t < NBLK2) ? g_bsums[t] : 0;
    sm[t] = v;
    __syncthreads();
    for (int d = 1; d < 128; d <<= 1) {
        int tmp = (t >= d) ? sm[t - d] : 0;
        __syncthreads();
        sm[t] += tmp;
        __syncthreads();
    }
    if (t < NBLK2) g_bsums[t] = sm[t] - v;   // exclusive
}

__global__ void mscanC_kernel() {
    int t = threadIdx.x;
    int base = blockIdx.x * 1024 + t * 4;
    int a[4], tsum = 0;
#pragma unroll
    for (int k = 0; k < 4; k++) {
        int v = base + k;
        a[k] = (v < NN) ? node_count(v) : 0;
        tsum += a[k];
    }
    __shared__ int sm[256];
    sm[t] = tsum;
    __syncthreads();
    for (int d = 1; d < 256; d <<= 1) {
        int tmp = (t >= d) ? sm[t - d] : 0;
        __syncthreads();
        sm[t] += tmp;
        __syncthreads();
    }
    int run = g_bsums[blockIdx.x] + sm[t] - tsum;
#pragma unroll
    for (int k = 0; k < 4; k++) {
        int v = base + k;
        if (v < NN) {
            g_moff[v] = run;
            g_mcnt[v] = a[k];
            g_mcur[v] = run;
            run += a[k];
        }
    }
}

// ---------------------------------------------------------------------------
// Fill self-loop + edge entries (flat row, fully precomputed weight)
// ---------------------------------------------------------------------------
__global__ void fillself_kernel() {
    int v = blockIdx.x * blockDim.x + threadIdx.x;
    if (v >= NN) return;
#pragma unroll
    for (int s = 0; s < NSETS; s++) {
        int pos = atomicAdd(&g_mcur[v], 1);
        float d = g_dis[s * NN + v];
        g_mrow[pos] = s * NPAD + v;
        g_mw[pos]   = d * d;
    }
}

__global__ void filledge_kernel(const int* __restrict__ e0, const int* __restrict__ e1,
                                const int* __restrict__ e2, const int* __restrict__ e3, int E) {
    int s = blockIdx.y;
    int e = blockIdx.x * blockDim.x + threadIdx.x;
    if (e >= E) return;
    const int* eg = (s == 0) ? e0 : (s == 1) ? e1 : (s == 2) ? e2 : e3;
    int row = __ldg(&eg[e]);
    int col = __ldg(&eg[E + e]);
    int pos = atomicAdd(&g_mcur[col], 1);
    g_mrow[pos] = s * NPAD + row;
    g_mw[pos]   = g_dis[s * NN + col] * g_dis[s * NN + row];
}

// ---------------------------------------------------------------------------
// fp16 GEMM (m16n8k16 HMMA): H[s][v][n] = sum_k x[v][k]*W'[s*256+n][k]
// A: g_xh [row][k] fp16, B: g_wh [n][k] fp16 (both K-major).
// CTA tile 128x128, BK=32, 8 warps, double-buffered cp.async. fp16 output.
// ---------------------------------------------------------------------------
#define BM 128
#define BN 128
#define BK 32
#define LDH 40    // halves per row in smem (80 bytes): conflict-free quads

static constexpr int SMEM_BYTES = (2 * BM * LDH + 2 * BN * LDH) * 2;  // 40960

__device__ __forceinline__ void cp_async16h(__half* smem_ptr, const __half* gmem_ptr, int src_bytes) {
    uint32_t saddr = (uint32_t)__cvta_generic_to_shared(smem_ptr);
    asm volatile("cp.async.cg.shared.global [%0], [%1], 16, %2;\n"
                 :: "r"(saddr), "l"(gmem_ptr), "r"(src_bytes));
}

__global__ __launch_bounds__(256, 2) void gemm_kernel(int n_rows) {
    extern __shared__ __half smh[];
    __half* Asm[2] = { smh, smh + BM * LDH };
    __half* Bsm[2] = { smh + 2 * BM * LDH, smh + 2 * BM * LDH + BN * LDH };

    const int tid   = threadIdx.x;
    const int lane  = tid & 31;
    const int warp  = tid >> 5;
    const int warpM = warp >> 2;   // 0..1  (64 rows)
    const int warpN = warp & 3;    // 0..3  (32 cols)
    const int m0 = blockIdx.y * BM;
    const int n0 = blockIdx.x * BN;     // 0..1023

    float acc[4][4][4];
#pragma unroll
    for (int i = 0; i < 4; i++)
#pragma unroll
        for (int j = 0; j < 4; j++)
#pragma unroll
            for (int k = 0; k < 4; k++) acc[i][j][k] = 0.f;

    auto loadA = [&](int buf, int kb) {
#pragma unroll
        for (int p = 0; p < 2; p++) {
            int idx = tid + p * 256;       // 512 chunks: 128 rows x 4 (8 halves each)
            int row = idx >> 2;
            int c8  = idx & 3;
            int gr  = m0 + row;
            const __half* src = g_xh + (size_t)gr * C + kb + c8 * 8;
            cp_async16h(&Asm[buf][row * LDH + c8 * 8], src, gr < n_rows ? 16 : 0);
        }
    };
    auto loadB = [&](int buf, int kb) {
#pragma unroll
        for (int p = 0; p < 2; p++) {
            int idx = tid + p * 256;       // 512 chunks: 128 n-rows x 4
            int row = idx >> 2;
            int c8  = idx & 3;
            const __half* src = g_wh + (size_t)(n0 + row) * C + kb + c8 * 8;
            cp_async16h(&Bsm[buf][row * LDH + c8 * 8], src, 16);
        }
    };

    loadA(0, 0); loadB(0, 0);
    asm volatile("cp.async.commit_group;\n");

#pragma unroll 1
    for (int kc = 0; kc < 8; kc++) {          // K = 256 = 8 * BK
        int cur = kc & 1;
        if (kc < 7) {
            loadA(cur ^ 1, (kc + 1) * BK);
            loadB(cur ^ 1, (kc + 1) * BK);
            asm volatile("cp.async.commit_group;\n");
            asm volatile("cp.async.wait_group 1;\n");
        } else {
            asm volatile("cp.async.wait_group 0;\n");
        }
        __syncthreads();

        const __half* Ab = Asm[cur];
        const __half* Bb = Bsm[cur];
#pragma unroll
        for (int kk = 0; kk < BK; kk += 16) {
            int kq = kk + (lane & 3) * 2;          // k pos for this lane
            uint32_t afr[4][4];
#pragma unroll
            for (int mt = 0; mt < 4; mt++) {
                int r = warpM * 64 + mt * 16 + (lane >> 2);
                afr[mt][0] = *(const uint32_t*)&Ab[r * LDH + kq];
                afr[mt][1] = *(const uint32_t*)&Ab[(r + 8) * LDH + kq];
                afr[mt][2] = *(const uint32_t*)&Ab[r * LDH + kq + 8];
                afr[mt][3] = *(const uint32_t*)&Ab[(r + 8) * LDH + kq + 8];
            }
            uint32_t bfr[4][2];
#pragma unroll
            for (int nt = 0; nt < 4; nt++) {
                int nb = warpN * 32 + nt * 8 + (lane >> 2);
                bfr[nt][0] = *(const uint32_t*)&Bb[nb * LDH + kq];
                bfr[nt][1] = *(const uint32_t*)&Bb[nb * LDH + kq + 8];
            }
#pragma unroll
            for (int mt = 0; mt < 4; mt++)
#pragma unroll
                for (int nt = 0; nt < 4; nt++)
                    asm volatile(
                        "mma.sync.aligned.m16n8k16.row.col.f32.f16.f16.f32 "
                        "{%0,%1,%2,%3}, {%4,%5,%6,%7}, {%8,%9}, {%0,%1,%2,%3};\n"
                        : "+f"(acc[mt][nt][0]), "+f"(acc[mt][nt][1]),
                          "+f"(acc[mt][nt][2]), "+f"(acc[mt][nt][3])
                        : "r"(afr[mt][0]), "r"(afr[mt][1]), "r"(afr[mt][2]), "r"(afr[mt][3]),
                          "r"(bfr[nt][0]), "r"(bfr[nt][1]));
        }
        __syncthreads();
    }

    // Epilogue: store H_s as fp16
    int s  = n0 >> 8;
    int nl = n0 & 255;
    __half* H = g_h + (size_t)s * NPAD * C;
#pragma unroll
    for (int mt = 0; mt < 4; mt++) {
        int r0 = m0 + warpM * 64 + mt * 16 + (lane >> 2);
#pragma unroll
        for (int nt = 0; nt < 4; nt++) {
            int cc = nl + warpN * 32 + nt * 8 + 2 * (lane & 3);
            if (r0 < n_rows)
                *(__half2*)&H[(size_t)r0 * C + cc] = __floats2half2_rn(acc[mt][nt][0], acc[mt][nt][1]);
            if (r0 + 8 < n_rows)
                *(__half2*)&H[(size_t)(r0 + 8) * C + cc] = __floats2half2_rn(acc[mt][nt][2], acc[mt][nt][3]);
        }
    }
}

// ---------------------------------------------------------------------------
// Aggregation over the MERGED per-node list (unchanged from R11)
// ---------------------------------------------------------------------------
__global__ __launch_bounds__(128) void agg_kernel(
        const float* __restrict__ x, const float* __restrict__ t0,
        const float* __restrict__ t1, const float* __restrict__ p0,
        const float* __restrict__ p1, float* __restrict__ out) {
    __shared__ int   sr[256];
    __shared__ float sw[256];

    int v = blockIdx.x;
    int tid = threadIdx.x;
    int c = tid * 2;
    float x0 = __ldg(&x[(size_t)v * C]);
    float a0 = x0 * __ldg(&t0[v]);
    float a1 = x0 * __ldg(&t1[v]);
    float accx = a0 * __ldg(&p0[c])     + a1 * __ldg(&p1[c])     + g_bsum[c];
    float accy = a0 * __ldg(&p0[c + 1]) + a1 * __ldg(&p1[c + 1]) + g_bsum[c + 1];

    const int off = g_moff[v];
    const int cnt = g_mcnt[v];

    for (int b0 = 0; b0 < cnt; b0 += 256) {
        int k = min(256, cnt - b0);
        __syncthreads();
        if (tid < k) {
            sr[tid] = __ldg(&g_mrow[off + b0 + tid]);
            sw[tid] = __ldg(&g_mw[off + b0 + tid]);
        }
        if (tid + 128 < k) {
            sr[tid + 128] = __ldg(&g_mrow[off + b0 + tid + 128]);
            sw[tid + 128] = __ldg(&g_mw[off + b0 + tid + 128]);
        }
        __syncthreads();
        int j = 0;
        for (; j + 4 <= k; j += 4) {
            int   r0 = sr[j],  r1 = sr[j + 1], r2 = sr[j + 2], r3 = sr[j + 3];
            float w0 = sw[j],  w1 = sw[j + 1], w2 = sw[j + 2], w3 = sw[j + 3];
            float2 f0 = __half22float2(*(const __half2*)&g_h[(size_t)r0 * C + c]);
            float2 f1 = __half22float2(*(const __half2*)&g_h[(size_t)r1 * C + c]);
            float2 f2 = __half22float2(*(const __half2*)&g_h[(size_t)r2 * C + c]);
            float2 f3 = __half22float2(*(const __half2*)&g_h[(size_t)r3 * C + c]);
            accx += w0 * f0.x + w1 * f1.x + w2 * f2.x + w3 * f3.x;
            accy += w0 * f0.y + w1 * f1.y + w2 * f2.y + w3 * f3.y;
        }
        for (; j < k; j++) {
            int   r0 = sr[j];
            float w0 = sw[j];
            float2 f0 = __half22float2(*(const __half2*)&g_h[(size_t)r0 * C + c]);
            accx += w0 * f0.x;
            accy += w0 * f0.y;
        }
    }
    *(float2*)&out[(size_t)v * C + c] = make_float2(accx, accy);
}

// ---------------------------------------------------------------------------
extern "C" void kernel_launch(void* const* d_in, const int* in_sizes, int n_in,
                              void* d_out, int out_size) {
    const float* x   = (const float*)d_in[0];
    const int* e00   = (const int*)d_in[1];
    const int* e01   = (const int*)d_in[2];
    const int* e10   = (const int*)d_in[3];
    const int* e11   = (const int*)d_in[4];
    const float* t0  = (const float*)d_in[5];
    const float* t1  = (const float*)d_in[6];
    const float* W1  = (const float*)d_in[7];
    const float* b1  = (const float*)d_in[8];
    const float* W2  = (const float*)d_in[9];
    const float* b2  = (const float*)d_in[10];
    const float* W3  = (const float*)d_in[11];
    const float* b3  = (const float*)d_in[12];
    const float* W4  = (const float*)d_in[13];
    const float* b4  = (const float*)d_in[14];
    const float* p0  = (const float*)d_in[15];
    const float* p1  = (const float*)d_in[16];
    const float* p2  = (const float*)d_in[17];
    const float* p3  = (const float*)d_in[18];
    const float* p4  = (const float*)d_in[19];
    const float* p5  = (const float*)d_in[20];

    const int E      = in_sizes[1] / 2;      // 500000
    const int n_rows = in_sizes[0] / C;      // 100000

    cudaFuncSetAttribute(gemm_kernel, cudaFuncAttributeMaxDynamicSharedMemorySize, SMEM_BYTES);

    prep_kernel<<<256, 256>>>(W1, W2, W3, W4, b1, b2, b3, b4, p2, p3, p4, p5);

    int n4 = n_rows * C / 4;
    xcvt_kernel<<<(n4 + 255) / 256, 256>>>(x, n4);

    dim3 dgrid((E + 255) / 256, NSETS);
    deg_kernel<<<dgrid, 256>>>(e00, e01, e10, e11, E);

    dis_kernel<<<(NT + 255) / 256, 256>>>();

    mscanA_kernel<<<NBLK2, 256>>>();
    mscanB_kernel<<<1, 128>>>();
    mscanC_kernel<<<NBLK2, 256>>>();

    fillself_kernel<<<(NN + 255) / 256, 256>>>();
    filledge_kernel<<<dgrid, 256>>>(e00, e01, e10, e11, E);

    dim3 ggrid((NSETS * C) / BN, (n_rows + BM - 1) / BM);
    gemm_kernel<<<ggrid, 256, SMEM_BYTES>>>(n_rows);

    agg_kernel<<<n_rows, 128>>>(x, t0, t1, p0, p1, (float*)d_out);
}

// round 16
// speedup vs baseline: 1.6700x; 1.0527x over previous
#include <cuda_runtime.h>
#include <cuda_fp16.h>
#include <cstdint>

// Problem constants (fixed instance)
#define NN    100000
#define NPAD  100096          // 782 * 128
#define C     256
#define NSETS 4
#define EMAX  500000
#define NT    (NSETS * NN)    // 400000
#define MCAP  (NSETS * (EMAX + NN))   // 2.4M merged entries
#define NBLK2 ((NN + 1023) / 1024)    // 98 scan blocks over nodes

// Persistent scratch (device globals — no allocation allowed)
__device__ __half   g_h[(size_t)NSETS * NPAD * C];   // ~205 MB fp16 H arena (flat rows)
__device__ __half   g_xh[(size_t)NPAD * C];          // ~51 MB x as fp16
__device__ float    g_dis[NT];                       // rsqrt(deg)
__device__ int      g_deg[NT];                       // 1 + in-edge count
__device__ int      g_moff[NN];                      // merged CSR offsets
__device__ int      g_mcnt[NN];                      // merged counts
__device__ int      g_mcur[NN];                      // fill cursors
__device__ int      g_mrow[MCAP];                    // flat H row index (s*NPAD + row)
__device__ float    g_mw[MCAP];                      // fully precomputed edge weight
__device__ int      g_bsums[256];                    // scan block sums
__device__ __half   g_wh[(NSETS * C) * C];           // [1024][256] fused weights, fp16, K-major
__device__ float    g_bsum[C];                       // Σ_s b_s ⊙ p_{s+2}

// ---------------------------------------------------------------------------
// Prep: g_wh[(s*256+n)][k] = half(W_s[k][n]*p_{s+2}[n]); bias; deg init = 1
// ---------------------------------------------------------------------------
__global__ void prep_kernel(const float* __restrict__ W1, const float* __restrict__ W2,
                            const float* __restrict__ W3, const float* __restrict__ W4,
                            const float* __restrict__ b1, const float* __restrict__ b2,
                            const float* __restrict__ b3, const float* __restrict__ b4,
                            const float* __restrict__ p2, const float* __restrict__ p3,
                            const float* __restrict__ p4, const float* __restrict__ p5) {
    int k = blockIdx.x;
    int n = threadIdx.x;
    g_wh[(size_t)(0 * 256 + n) * 256 + k] = __float2half_rn(W1[k * 256 + n] * p2[n]);
    g_wh[(size_t)(1 * 256 + n) * 256 + k] = __float2half_rn(W2[k * 256 + n] * p3[n]);
    g_wh[(size_t)(2 * 256 + n) * 256 + k] = __float2half_rn(W3[k * 256 + n] * p4[n]);
    g_wh[(size_t)(3 * 256 + n) * 256 + k] = __float2half_rn(W4[k * 256 + n] * p5[n]);
    if (k == 0)
        g_bsum[n] = b1[n] * p2[n] + b2[n] * p3[n] + b3[n] * p4[n] + b4[n] * p5[n];
    int idx = k * 256 + n;
    for (int i = idx; i < NT; i += 256 * 256) g_deg[i] = 1;
}

// ---------------------------------------------------------------------------
// x -> fp16 (vectorized: 4 floats -> 4 halves per thread)
// ---------------------------------------------------------------------------
__global__ void xcvt_kernel(const float* __restrict__ x, int n4) {
    int i = blockIdx.x * blockDim.x + threadIdx.x;
    if (i >= n4) return;
    float4 v = __ldg((const float4*)x + i);
    __half2 h0 = __floats2half2_rn(v.x, v.y);
    __half2 h1 = __floats2half2_rn(v.z, v.w);
    uint2 o;
    o.x = *(const uint32_t*)&h0;
    o.y = *(const uint32_t*)&h1;
    ((uint2*)g_xh)[i] = o;
}

// ---------------------------------------------------------------------------
// Degree count
// ---------------------------------------------------------------------------
__global__ void deg_kernel(const int* __restrict__ e0, const int* __restrict__ e1,
                           const int* __restrict__ e2, const int* __restrict__ e3, int E) {
    int s = blockIdx.y;
    int e = blockIdx.x * blockDim.x + threadIdx.x;
    if (e >= E) return;
    const int* eg = (s == 0) ? e0 : (s == 1) ? e1 : (s == 2) ? e2 : e3;
    atomicAdd(&g_deg[s * NN + __ldg(&eg[E + e])], 1);
}

__global__ void dis_kernel() {
    int i = blockIdx.x * blockDim.x + threadIdx.x;
    if (i < NT) g_dis[i] = rsqrtf((float)g_deg[i]);
}

// ---------------------------------------------------------------------------
// Exclusive scan over merged per-node counts: cnt(v) = Σ_s deg[s,v]
// ---------------------------------------------------------------------------
__device__ __forceinline__ int node_count(int v) {
    return g_deg[v] + g_deg[NN + v] + g_deg[2 * NN + v] + g_deg[3 * NN + v];
}

__global__ void mscanA_kernel() {
    int t = threadIdx.x;
    int base = blockIdx.x * 1024 + t * 4;
    int s = 0;
#pragma unroll
    for (int k = 0; k < 4; k++) {
        int v = base + k;
        if (v < NN) s += node_count(v);
    }
    __shared__ int sm[256];
    sm[t] = s;
    __syncthreads();
    for (int d = 128; d > 0; d >>= 1) {
        if (t < d) sm[t] += sm[t + d];
        __syncthreads();
    }
    if (t == 0) g_bsums[blockIdx.x] = sm[0];
}

__global__ void mscanB_kernel() {
    int t = threadIdx.x;   // 128 threads >= NBLK2 (98)
    __shared__ int sm[128];
    int v = (t < NBLK2) ? g_bsums[t] : 0;
    sm[t] = v;
    __syncthreads();
    for (int d = 1; d < 128; d <<= 1) {
        int tmp = (t >= d) ? sm[t - d] : 0;
        __syncthreads();
        sm[t] += tmp;
        __syncthreads();
    }
    if (t < NBLK2) g_bsums[t] = sm[t] - v;   // exclusive
}

__global__ void mscanC_kernel() {
    int t = threadIdx.x;
    int base = blockIdx.x * 1024 + t * 4;
    int a[4], tsum = 0;
#pragma unroll
    for (int k = 0; k < 4; k++) {
        int v = base + k;
        a[k] = (v < NN) ? node_count(v) : 0;
        tsum += a[k];
    }
    __shared__ int sm[256];
    sm[t] = tsum;
    __syncthreads();
    for (int d = 1; d < 256; d <<= 1) {
        int tmp = (t >= d) ? sm[t - d] : 0;
        __syncthreads();
        sm[t] += tmp;
        __syncthreads();
    }
    int run = g_bsums[blockIdx.x] + sm[t] - tsum;
#pragma unroll
    for (int k = 0; k < 4; k++) {
        int v = base + k;
        if (v < NN) {
            g_moff[v] = run;
            g_mcnt[v] = a[k];
            g_mcur[v] = run;
            run += a[k];
        }
    }
}

// ---------------------------------------------------------------------------
// Fill self-loop + edge entries (flat row, fully precomputed weight)
// ---------------------------------------------------------------------------
__global__ void fillself_kernel() {
    int v = blockIdx.x * blockDim.x + threadIdx.x;
    if (v >= NN) return;
#pragma unroll
    for (int s = 0; s < NSETS; s++) {
        int pos = atomicAdd(&g_mcur[v], 1);
        float d = g_dis[s * NN + v];
        g_mrow[pos] = s * NPAD + v;
        g_mw[pos]   = d * d;
    }
}

__global__ void filledge_kernel(const int* __restrict__ e0, const int* __restrict__ e1,
                                const int* __restrict__ e2, const int* __restrict__ e3, int E) {
    int s = blockIdx.y;
    int e = blockIdx.x * blockDim.x + threadIdx.x;
    if (e >= E) return;
    const int* eg = (s == 0) ? e0 : (s == 1) ? e1 : (s == 2) ? e2 : e3;
    int row = __ldg(&eg[e]);
    int col = __ldg(&eg[E + e]);
    int pos = atomicAdd(&g_mcur[col], 1);
    g_mrow[pos] = s * NPAD + row;
    g_mw[pos]   = g_dis[s * NN + col] * g_dis[s * NN + row];
}

// ---------------------------------------------------------------------------
// fp16 GEMM (m16n8k16 HMMA + ldmatrix): H[s][v][n] = sum_k x[v][k]*W'[n'][k]
// A: g_xh [row][k] fp16, B: g_wh [n][k] fp16 (both K-major).
// CTA tile 128x128, BK=32, 8 warps, double-buffered cp.async. fp16 output.
// ---------------------------------------------------------------------------
#define BM 128
#define BN 128
#define BK 32
#define LDH 40    // halves per row in smem (80 bytes): LDSM rows hit distinct banks

static constexpr int SMEM_BYTES = (2 * BM * LDH + 2 * BN * LDH) * 2;  // 40960

__device__ __forceinline__ void cp_async16h(__half* smem_ptr, const __half* gmem_ptr, int src_bytes) {
    uint32_t saddr = (uint32_t)__cvta_generic_to_shared(smem_ptr);
    asm volatile("cp.async.cg.shared.global [%0], [%1], 16, %2;\n"
                 :: "r"(saddr), "l"(gmem_ptr), "r"(src_bytes));
}
__device__ __forceinline__ void ldsm_x4(uint32_t& r0, uint32_t& r1, uint32_t& r2, uint32_t& r3,
                                        const __half* p) {
    uint32_t a = (uint32_t)__cvta_generic_to_shared(p);
    asm volatile("ldmatrix.sync.aligned.m8n8.x4.shared.b16 {%0,%1,%2,%3}, [%4];"
                 : "=r"(r0), "=r"(r1), "=r"(r2), "=r"(r3) : "r"(a));
}

__global__ __launch_bounds__(256, 2) void gemm_kernel(int n_rows) {
    extern __shared__ __half smh[];
    __half* Asm[2] = { smh, smh + BM * LDH };
    __half* Bsm[2] = { smh + 2 * BM * LDH, smh + 2 * BM * LDH + BN * LDH };

    const int tid   = threadIdx.x;
    const int lane  = tid & 31;
    const int warp  = tid >> 5;
    const int warpM = warp >> 2;   // 0..1  (64 rows)
    const int warpN = warp & 3;    // 0..3  (32 cols)
    const int m0 = blockIdx.y * BM;
    const int n0 = blockIdx.x * BN;     // 0..1023

    float acc[4][4][4];
#pragma unroll
    for (int i = 0; i < 4; i++)
#pragma unroll
        for (int j = 0; j < 4; j++)
#pragma unroll
            for (int k = 0; k < 4; k++) acc[i][j][k] = 0.f;

    auto loadA = [&](int buf, int kb) {
#pragma unroll
        for (int p = 0; p < 2; p++) {
            int idx = tid + p * 256;       // 512 chunks: 128 rows x 4 (8 halves each)
            int row = idx >> 2;
            int c8  = idx & 3;
            int gr  = m0 + row;
            const __half* src = g_xh + (size_t)gr * C + kb + c8 * 8;
            cp_async16h(&Asm[buf][row * LDH + c8 * 8], src, gr < n_rows ? 16 : 0);
        }
    };
    auto loadB = [&](int buf, int kb) {
#pragma unroll
        for (int p = 0; p < 2; p++) {
            int idx = tid + p * 256;       // 512 chunks: 128 n-rows x 4
            int row = idx >> 2;
            int c8  = idx & 3;
            const __half* src = g_wh + (size_t)(n0 + row) * C + kb + c8 * 8;
            cp_async16h(&Bsm[buf][row * LDH + c8 * 8], src, 16);
        }
    };

    // ldmatrix lane address components (constant across kk/kc)
    const int aRowSel = lane & 15;         // A: row within 16-row tile
    const int aKSel   = (lane >> 4) * 8;   // A: k-half select
    const int bNSel   = ((lane >> 4) * 8) + (lane & 7);  // B: n row within 16
    const int bKSel   = ((lane >> 3) & 1) * 8;           // B: k-half select

    loadA(0, 0); loadB(0, 0);
    asm volatile("cp.async.commit_group;\n");

#pragma unroll 1
    for (int kc = 0; kc < 8; kc++) {          // K = 256 = 8 * BK
        int cur = kc & 1;
        if (kc < 7) {
            loadA(cur ^ 1, (kc + 1) * BK);
            loadB(cur ^ 1, (kc + 1) * BK);
            asm volatile("cp.async.commit_group;\n");
            asm volatile("cp.async.wait_group 1;\n");
        } else {
            asm volatile("cp.async.wait_group 0;\n");
        }
        __syncthreads();

        const __half* Ab = Asm[cur];
        const __half* Bb = Bsm[cur];
#pragma unroll
        for (int kk = 0; kk < BK; kk += 16) {
            uint32_t afr[4][4];
#pragma unroll
            for (int mt = 0; mt < 4; mt++) {
                int r = warpM * 64 + mt * 16 + aRowSel;
                ldsm_x4(afr[mt][0], afr[mt][1], afr[mt][2], afr[mt][3],
                        &Ab[r * LDH + kk + aKSel]);
            }
            uint32_t bfr[4][2];
#pragma unroll
            for (int pr = 0; pr < 2; pr++) {   // each LDSM.x4 covers two n8 tiles
                int nb = warpN * 32 + pr * 16 + bNSel;
                ldsm_x4(bfr[pr * 2][0], bfr[pr * 2][1], bfr[pr * 2 + 1][0], bfr[pr * 2 + 1][1],
                        &Bb[nb * LDH + kk + bKSel]);
            }
#pragma unroll
            for (int mt = 0; mt < 4; mt++)
#pragma unroll
                for (int nt = 0; nt < 4; nt++)
                    asm volatile(
                        "mma.sync.aligned.m16n8k16.row.col.f32.f16.f16.f32 "
                        "{%0,%1,%2,%3}, {%4,%5,%6,%7}, {%8,%9}, {%0,%1,%2,%3};\n"
                        : "+f"(acc[mt][nt][0]), "+f"(acc[mt][nt][1]),
                          "+f"(acc[mt][nt][2]), "+f"(acc[mt][nt][3])
                        : "r"(afr[mt][0]), "r"(afr[mt][1]), "r"(afr[mt][2]), "r"(afr[mt][3]),
                          "r"(bfr[nt][0]), "r"(bfr[nt][1]));
        }
        __syncthreads();
    }

    // Epilogue: store H_s as fp16
    int s  = n0 >> 8;
    int nl = n0 & 255;
    __half* H = g_h + (size_t)s * NPAD * C;
#pragma unroll
    for (int mt = 0; mt < 4; mt++) {
        int r0 = m0 + warpM * 64 + mt * 16 + (lane >> 2);
#pragma unroll
        for (int nt = 0; nt < 4; nt++) {
            int cc = nl + warpN * 32 + nt * 8 + 2 * (lane & 3);
            if (r0 < n_rows)
                *(__half2*)&H[(size_t)r0 * C + cc] = __floats2half2_rn(acc[mt][nt][0], acc[mt][nt][1]);
            if (r0 + 8 < n_rows)
                *(__half2*)&H[(size_t)(r0 + 8) * C + cc] = __floats2half2_rn(acc[mt][nt][2], acc[mt][nt][3]);
        }
    }
}

// ---------------------------------------------------------------------------
// Aggregation over the MERGED per-node list (unchanged from R11)
// ---------------------------------------------------------------------------
__global__ __launch_bounds__(128) void agg_kernel(
        const float* __restrict__ x, const float* __restrict__ t0,
        const float* __restrict__ t1, const float* __restrict__ p0,
        const float* __restrict__ p1, float* __restrict__ out) {
    __shared__ int   sr[256];
    __shared__ float sw[256];

    int v = blockIdx.x;
    int tid = threadIdx.x;
    int c = tid * 2;
    float x0 = __ldg(&x[(size_t)v * C]);
    float a0 = x0 * __ldg(&t0[v]);
    float a1 = x0 * __ldg(&t1[v]);
    float accx = a0 * __ldg(&p0[c])     + a1 * __ldg(&p1[c])     + g_bsum[c];
    float accy = a0 * __ldg(&p0[c + 1]) + a1 * __ldg(&p1[c + 1]) + g_bsum[c + 1];

    const int off = g_moff[v];
    const int cnt = g_mcnt[v];

    for (int b0 = 0; b0 < cnt; b0 += 256) {
        int k = min(256, cnt - b0);
        __syncthreads();
        if (tid < k) {
            sr[tid] = __ldg(&g_mrow[off + b0 + tid]);
            sw[tid] = __ldg(&g_mw[off + b0 + tid]);
        }
        if (tid + 128 < k) {
            sr[tid + 128] = __ldg(&g_mrow[off + b0 + tid + 128]);
            sw[tid + 128] = __ldg(&g_mw[off + b0 + tid + 128]);
        }
        __syncthreads();
        int j = 0;
        for (; j + 4 <= k; j += 4) {
            int   r0 = sr[j],  r1 = sr[j + 1], r2 = sr[j + 2], r3 = sr[j + 3];
            float w0 = sw[j],  w1 = sw[j + 1], w2 = sw[j + 2], w3 = sw[j + 3];
            float2 f0 = __half22float2(*(const __half2*)&g_h[(size_t)r0 * C + c]);
            float2 f1 = __half22float2(*(const __half2*)&g_h[(size_t)r1 * C + c]);
            float2 f2 = __half22float2(*(const __half2*)&g_h[(size_t)r2 * C + c]);
            float2 f3 = __half22float2(*(const __half2*)&g_h[(size_t)r3 * C + c]);
            accx += w0 * f0.x + w1 * f1.x + w2 * f2.x + w3 * f3.x;
            accy += w0 * f0.y + w1 * f1.y + w2 * f2.y + w3 * f3.y;
        }
        for (; j < k; j++) {
            int   r0 = sr[j];
            float w0 = sw[j];
            float2 f0 = __half22float2(*(const __half2*)&g_h[(size_t)r0 * C + c]);
            accx += w0 * f0.x;
            accy += w0 * f0.y;
        }
    }
    *(float2*)&out[(size_t)v * C + c] = make_float2(accx, accy);
}

// ---------------------------------------------------------------------------
extern "C" void kernel_launch(void* const* d_in, const int* in_sizes, int n_in,
                              void* d_out, int out_size) {
    const float* x   = (const float*)d_in[0];
    const int* e00   = (const int*)d_in[1];
    const int* e01   = (const int*)d_in[2];
    const int* e10   = (const int*)d_in[3];
    const int* e11   = (const int*)d_in[4];
    const float* t0  = (const float*)d_in[5];
    const float* t1  = (const float*)d_in[6];
    const float* W1  = (const float*)d_in[7];
    const float* b1  = (const float*)d_in[8];
    const float* W2  = (const float*)d_in[9];
    const float* b2  = (const float*)d_in[10];
    const float* W3  = (const float*)d_in[11];
    const float* b3  = (const float*)d_in[12];
    const float* W4  = (const float*)d_in[13];
    const float* b4  = (const float*)d_in[14];
    const float* p0  = (const float*)d_in[15];
    const float* p1  = (const float*)d_in[16];
    const float* p2  = (const float*)d_in[17];
    const float* p3  = (const float*)d_in[18];
    const float* p4  = (const float*)d_in[19];
    const float* p5  = (const float*)d_in[20];

    const int E      = in_sizes[1] / 2;      // 500000
    const int n_rows = in_sizes[0] / C;      // 100000

    cudaFuncSetAttribute(gemm_kernel, cudaFuncAttributeMaxDynamicSharedMemorySize, SMEM_BYTES);

    prep_kernel<<<256, 256>>>(W1, W2, W3, W4, b1, b2, b3, b4, p2, p3, p4, p5);

    int n4 = n_rows * C / 4;
    xcvt_kernel<<<(n4 + 255) / 256, 256>>>(x, n4);

    dim3 dgrid((E + 255) / 256, NSETS);
    deg_kernel<<<dgrid, 256>>>(e00, e01, e10, e11, E);

    dis_kernel<<<(NT + 255) / 256, 256>>>();

    mscanA_kernel<<<NBLK2, 256>>>();
    mscanB_kernel<<<1, 128>>>();
    mscanC_kernel<<<NBLK2, 256>>>();

    fillself_kernel<<<(NN + 255) / 256, 256>>>();
    filledge_kernel<<<dgrid, 256>>>(e00, e01, e10, e11, E);

    dim3 ggrid((NSETS * C) / BN, (n_rows + BM - 1) / BM);
    gemm_kernel<<<ggrid, 256, SMEM_BYTES>>>(n_rows);

    agg_kernel<<<n_rows, 128>>>(x, t0, t1, p0, p1, (float*)d_out);
}